// round 17
// baseline (speedup 1.0000x reference)
#include <cuda_runtime.h>
#include <cuda_fp16.h>
#include <cstdint>

// Problem constants
#define TSTEPS 8192
#define MDIM   2048   // mem_dim
#define GDIM   8192   // 4*mem_dim
#define KDIM   2048   // in_dim

// Recurrence kernel config
#define NCTA   128            // co-resident CTAs (GB300 has 152 SMs)
#define NTH    512            // 16 warps; warp w owns hidden unit j = cta*16 + w
#define JPC    16             // MDIM / NCTA
// smem: h fp16 (2048*2 = 4KB) + 48 weight rows (gates 0..2) fp16 = 192KB
#define REC_SMEM (MDIM * 2 + 48 * MDIM * 2)   // 200704 B

// Scratch (static __device__ arrays: the sanctioned no-alloc workaround)
__device__ float  g_xproj[(size_t)TSTEPS * GDIM];   // 256 MB
__device__ __half g_wh16[(size_t)GDIM * MDIM];      // 32 MB fp16 copy of Wh
__device__ __half g_h16[2][MDIM];                   // double-buffered hidden state (fp16)
__device__ unsigned int          g_cnt;             // init-barrier arrival counter
__device__ volatile unsigned int g_gen;             // init-barrier generation (monotonic)
__device__ unsigned int          g_flags[NCTA];     // per-CTA step flags (barrier)

typedef unsigned long long ull;

// ---------------------------------------------------------------------------
// f32x2 packed-FMA helpers (GEMM)
// ---------------------------------------------------------------------------
__device__ __forceinline__ ull dup2(float a) {
    ull r;
    asm("mov.b64 %0, {%1, %1};" : "=l"(r) : "f"(a));
    return r;
}
__device__ __forceinline__ void fma2(ull& acc, ull a, ull b) {
    asm("fma.rn.f32x2 %0, %1, %2, %0;" : "+l"(acc) : "l"(a), "l"(b));
}
__device__ __forceinline__ void unpack2(ull v, float& lo, float& hi) {
    asm("mov.b64 {%0, %1}, %2;" : "=f"(lo), "=f"(hi) : "l"(v));
}

// ---------------------------------------------------------------------------
// Mixed-precision dot: 8 fp16 weights (uint4) * 8 fp16 h (uint4) -> f32 acc.
// ---------------------------------------------------------------------------
__device__ __forceinline__ void gate8(float& acc, uint4 w, uint4 h) {
    asm("{\n\t"
        ".reg .b16 a0,a1,a2,a3,a4,a5,a6,a7;\n\t"
        ".reg .b16 b0,b1,b2,b3,b4,b5,b6,b7;\n\t"
        "mov.b32 {a0,a1}, %1;\n\t"
        "mov.b32 {a2,a3}, %2;\n\t"
        "mov.b32 {a4,a5}, %3;\n\t"
        "mov.b32 {a6,a7}, %4;\n\t"
        "mov.b32 {b0,b1}, %5;\n\t"
        "mov.b32 {b2,b3}, %6;\n\t"
        "mov.b32 {b4,b5}, %7;\n\t"
        "mov.b32 {b6,b7}, %8;\n\t"
        "fma.rn.f32.f16 %0, a0, b0, %0;\n\t"
        "fma.rn.f32.f16 %0, a1, b1, %0;\n\t"
        "fma.rn.f32.f16 %0, a2, b2, %0;\n\t"
        "fma.rn.f32.f16 %0, a3, b3, %0;\n\t"
        "fma.rn.f32.f16 %0, a4, b4, %0;\n\t"
        "fma.rn.f32.f16 %0, a5, b5, %0;\n\t"
        "fma.rn.f32.f16 %0, a6, b6, %0;\n\t"
        "fma.rn.f32.f16 %0, a7, b7, %0;\n\t"
        "}"
        : "+f"(acc)
        : "r"(w.x), "r"(w.y), "r"(w.z), "r"(w.w),
          "r"(h.x), "r"(h.y), "r"(h.z), "r"(h.w));
}

// ---------------------------------------------------------------------------
// Kernel P: Wh fp32 -> fp16 (natural [G][K] layout)
// ---------------------------------------------------------------------------
__global__ void wh_to_half(const float* __restrict__ Wh)
{
    size_t i = ((size_t)blockIdx.x * blockDim.x + threadIdx.x) * 4;
    float4 v = *(const float4*)(Wh + i);
    __half2* dst = (__half2*)(g_wh16 + i);
    dst[0] = __floats2half2_rn(v.x, v.y);
    dst[1] = __floats2half2_rn(v.z, v.w);
}

// ---------------------------------------------------------------------------
// Kernel A: x_proj = inputs @ Wx^T + bx + bh  (128x128x16 tiles, f32x2 FMAs)
// ---------------------------------------------------------------------------
#define BM 128
#define BN 128
#define BK 16
#define TM 8
#define TN 8

__global__ __launch_bounds__(256, 2)
void xproj_gemm(const float* __restrict__ A,
                const float* __restrict__ B,
                const float* __restrict__ bx,
                const float* __restrict__ bh)
{
    __shared__ __align__(16) float As[BK][BM];
    __shared__ __align__(16) float Bs[BK][BN];

    const int tid = threadIdx.x;
    const int tx  = tid & 15;
    const int ty  = tid >> 4;

    const float* Ab = A + (size_t)blockIdx.y * BM * KDIM;
    const float* Bb = B + (size_t)blockIdx.x * BN * KDIM;

    ull acc2[TM][TN / 2];
#pragma unroll
    for (int i = 0; i < TM; i++)
#pragma unroll
        for (int jp = 0; jp < TN / 2; jp++) acc2[i][jp] = 0ull;

    for (int k0 = 0; k0 < KDIM; k0 += BK) {
#pragma unroll
        for (int r = 0; r < 2; r++) {
            int i   = tid + r * 256;
            int row = i >> 2;
            int kq  = (i & 3) * 4;
            float4 va = *(const float4*)(Ab + (size_t)row * KDIM + k0 + kq);
            As[kq + 0][row] = va.x; As[kq + 1][row] = va.y;
            As[kq + 2][row] = va.z; As[kq + 3][row] = va.w;
            float4 vb = *(const float4*)(Bb + (size_t)row * KDIM + k0 + kq);
            Bs[kq + 0][row] = vb.x; Bs[kq + 1][row] = vb.y;
            Bs[kq + 2][row] = vb.z; Bs[kq + 3][row] = vb.w;
        }
        __syncthreads();

#pragma unroll
        for (int kk = 0; kk < BK; kk++) {
            const float4* pa = (const float4*)&As[kk][ty * TM];
            const ull*    pb = (const ull*)&Bs[kk][tx * TN];
            float4 a0 = pa[0], a1 = pa[1];
            ull bb0 = pb[0], bb1 = pb[1], bb2 = pb[2], bb3 = pb[3];
            ull ad[TM];
            ad[0] = dup2(a0.x); ad[1] = dup2(a0.y);
            ad[2] = dup2(a0.z); ad[3] = dup2(a0.w);
            ad[4] = dup2(a1.x); ad[5] = dup2(a1.y);
            ad[6] = dup2(a1.z); ad[7] = dup2(a1.w);
#pragma unroll
            for (int i = 0; i < TM; i++) {
                fma2(acc2[i][0], ad[i], bb0);
                fma2(acc2[i][1], ad[i], bb1);
                fma2(acc2[i][2], ad[i], bb2);
                fma2(acc2[i][3], ad[i], bb3);
            }
        }
        __syncthreads();
    }

    const int grow = blockIdx.y * BM + ty * TM;
    const int gcol = blockIdx.x * BN + tx * TN;
    float bias[TN];
#pragma unroll
    for (int j = 0; j < TN; j++) bias[j] = bx[gcol + j] + bh[gcol + j];

#pragma unroll
    for (int i = 0; i < TM; i++) {
        float v[TN];
#pragma unroll
        for (int jp = 0; jp < TN / 2; jp++)
            unpack2(acc2[i][jp], v[2 * jp], v[2 * jp + 1]);
        float4 o0, o1;
        o0.x = v[0] + bias[0]; o0.y = v[1] + bias[1];
        o0.z = v[2] + bias[2]; o0.w = v[3] + bias[3];
        o1.x = v[4] + bias[4]; o1.y = v[5] + bias[5];
        o1.z = v[6] + bias[6]; o1.w = v[7] + bias[7];
        float4* dst = (float4*)(g_xproj + (size_t)(grow + i) * GDIM + gcol);
        dst[0] = o0;
        dst[1] = o1;
    }
}

// ---------------------------------------------------------------------------
// Init barrier (gen-based; used ONCE per launch, after per-CTA flag reset).
// ---------------------------------------------------------------------------
__device__ __forceinline__ void init_bar()
{
    __syncthreads();
    if (threadIdx.x == 0) {
        unsigned gen = g_gen;
        __threadfence();
        unsigned arrived = atomicAdd(&g_cnt, 1);
        if (arrived == NCTA - 1) {
            g_cnt = 0;
            __threadfence();
            g_gen = gen + 1;       // release
        } else {
            while (g_gen == gen) { }
        }
        __threadfence();           // acquire
    }
    __syncthreads();
}

// ---------------------------------------------------------------------------
// Kernel B: persistent LSTM recurrence.
//   Wh fully on-chip fp16 (48 rows smem + 16 reg-resident u rows per CTA).
//   h broadcast as fp16 (4KB). Grid sync = per-CTA flag stores (no atomics)
//   + warp-0 vector poll with MLP-4 relaxed loads.
// ---------------------------------------------------------------------------
__global__ void __launch_bounds__(NTH, 1)
lstm_rec(float* __restrict__ out)
{
    extern __shared__ char smraw[];
    __half* h16 = (__half*)smraw;                       // 2048 fp16
    __half* w_s = (__half*)(smraw + MDIM * 2);          // 48 rows x 2048 fp16

    const int tid  = threadIdx.x;
    const int lane = tid & 31;
    const int w    = tid >> 5;
    const int cta  = blockIdx.x;
    const int j    = cta * JPC + w;      // global hidden unit

    // one-time: gates 0..2 rows into smem
#pragma unroll
    for (int g = 0; g < 3; g++) {
        const uint4* src = (const uint4*)(g_wh16 + ((size_t)(g * MDIM + j)) * MDIM);
        uint4*       dst = (uint4*)(w_s + (size_t)(g * 16 + w) * MDIM);
#pragma unroll
        for (int r = 0; r < 8; r++)
            dst[lane + 32 * r] = src[lane + 32 * r];
    }

    // one-time: u-gate row into registers (uint4 = 8 fp16)
    uint4 wreg[8];
    {
        const uint4* src = (const uint4*)(g_wh16 + ((size_t)(3 * MDIM + j)) * MDIM);
#pragma unroll
        for (int ii = 0; ii < 8; ii++)
            wreg[ii] = src[lane + 32 * ii];
    }

    const uint4* ws4 = (const uint4*)w_s;
    const uint4* r0 = ws4 + (size_t)(0 * 16 + w) * (MDIM / 8);
    const uint4* r1 = ws4 + (size_t)(1 * 16 + w) * (MDIM / 8);
    const uint4* r2 = ws4 + (size_t)(2 * 16 + w) * (MDIM / 8);

    // launch-start reset (ordered before everyone proceeds by init_bar)
    if (lane == 0) {
        *(__half*)&g_h16[0][j] = __float2half_rn(0.f);
        if (w == 0) g_flags[cta] = 0u;
    }
    float cval = 0.f, hval = 0.f;
    __threadfence();
    init_bar();

    for (int t = 0; t < TSTEPS; t++) {
        // snapshot h_prev (fp16, 4KB) -> smem; other SMs wrote it, bypass L1
        ((uint2*)h16)[tid] = __ldcg(((const uint2*)g_h16[t & 1]) + tid);
        __syncthreads();

        // prefetch x_proj for this step (independent of h; overlaps dot loop)
        float xp0 = 0.f, xp1 = 0.f, xp2 = 0.f, xp3 = 0.f;
        if (lane == 0) {
            const float* xr = g_xproj + (size_t)t * GDIM + j;
            xp0 = __ldcs(xr);
            xp1 = __ldcs(xr + MDIM);
            xp2 = __ldcs(xr + 2 * MDIM);
            xp3 = __ldcs(xr + 3 * MDIM);
        }

        float a0 = 0.f, a1 = 0.f, a2 = 0.f, a3 = 0.f;
#pragma unroll
        for (int ii = 0; ii < 8; ii++) {
            const int idx = lane + 32 * ii;
            uint4 hv = ((const uint4*)h16)[idx];   // 8 fp16 h values
            gate8(a0, r0[idx],   hv);
            gate8(a1, r1[idx],   hv);
            gate8(a2, r2[idx],   hv);
            gate8(a3, wreg[ii],  hv);
        }

#pragma unroll
        for (int off = 16; off > 0; off >>= 1) {
            a0 += __shfl_xor_sync(0xffffffffu, a0, off);
            a1 += __shfl_xor_sync(0xffffffffu, a1, off);
            a2 += __shfl_xor_sync(0xffffffffu, a2, off);
            a3 += __shfl_xor_sync(0xffffffffu, a3, off);
        }

        if (lane == 0) {
            float zi = xp0 + a0;
            float zo = xp1 + a1;
            float zf = xp2 + a2;
            float zu = xp3 + a3;
            float ig = 1.f / (1.f + __expf(-zi));
            float og = 1.f / (1.f + __expf(-zo));
            float fg = 1.f / (1.f + __expf(-zf));
            float ug = 2.f / (1.f + __expf(-2.f * zu)) - 1.f;
            cval = fmaf(ig, ug, fg * cval);
            float tc = 2.f / (1.f + __expf(-2.f * cval)) - 1.f;
            hval = og * tc;
            *(__half*)&g_h16[(t & 1) ^ 1][j] = __float2half_rn(hval);
        }

        // ---- grid barrier: per-CTA flag store + warp-0 vector poll ----
        __syncthreads();                       // all warps' h stores issued
        if (tid == 0) {
            asm volatile("st.release.gpu.global.u32 [%0], %1;"
                         :: "l"(g_flags + cta), "r"((unsigned)(t + 1)) : "memory");
        }
        if (w == 0) {
            const unsigned target = (unsigned)(t + 1);
            unsigned f0, f1, f2, f3;
            bool ok;
            do {
                asm volatile("ld.relaxed.gpu.global.u32 %0, [%4];\n\t"
                             "ld.relaxed.gpu.global.u32 %1, [%5];\n\t"
                             "ld.relaxed.gpu.global.u32 %2, [%6];\n\t"
                             "ld.relaxed.gpu.global.u32 %3, [%7];"
                             : "=r"(f0), "=r"(f1), "=r"(f2), "=r"(f3)
                             : "l"(g_flags + lane),      "l"(g_flags + lane + 32),
                               "l"(g_flags + lane + 64), "l"(g_flags + lane + 96)
                             : "memory");
                ok = (f0 >= target) & (f1 >= target) & (f2 >= target) & (f3 >= target);
            } while (!__all_sync(0xffffffffu, ok));
            asm volatile("fence.acq_rel.gpu;" ::: "memory");
        }
        __syncthreads();                       // release whole CTA
    }

    if (lane == 0) out[j] = hval;
}

// ---------------------------------------------------------------------------
extern "C" void kernel_launch(void* const* d_in, const int* in_sizes, int n_in,
                              void* d_out, int out_size)
{
    (void)in_sizes; (void)n_in; (void)out_size;
    const float* inputs = (const float*)d_in[0];   // (T,1,2048)
    const float* Wx     = (const float*)d_in[1];   // (8192,2048)
    const float* bx     = (const float*)d_in[2];   // (8192,)
    const float* Wh     = (const float*)d_in[3];   // (8192,2048)
    const float* bh     = (const float*)d_in[4];   // (8192,)
    float* out = (float*)d_out;                    // (1,2048)

    cudaFuncSetAttribute(lstm_rec, cudaFuncAttributeMaxDynamicSharedMemorySize,
                         (int)REC_SMEM);

    wh_to_half<<<(GDIM * (MDIM / 4)) / 256, 256>>>(Wh);

    dim3 ggrid(GDIM / BN, TSTEPS / BM);   // 64 x 64
    xproj_gemm<<<ggrid, 256>>>(inputs, Wx, bx, bh);

    lstm_rec<<<NCTA, NTH, REC_SMEM>>>(out);
}